// round 11
// baseline (speedup 1.0000x reference)
#include <cuda_runtime.h>
#include <math.h>
#include <stdint.h>

// Problem constants
#define L_SEQ   2048
#define D_MODEL 2048
#define QKV_DIM 3072   // (16 + 2*4) * 128
#define NQH     16
#define NKVH    4
#define HD      128
#define WINDOW  1024

// Scratch (static device allocations; no cudaMalloc allowed)
__device__ uint32_t g_xt[L_SEQ * D_MODEL];        // x as tf32 bits, [m][k]
__device__ uint32_t g_wqkvt[QKV_DIM * D_MODEL];   // Wqkv^T tf32 bits, [n][k]
__device__ uint32_t g_wot[D_MODEL * D_MODEL];     // Wo^T tf32 bits, [n][k]
__device__ float    g_proj[L_SEQ * QKV_DIM];      // fp32 after GEMM; tf32 bits after rope
__device__ uint32_t g_attn[L_SEQ * D_MODEL];      // attention out, tf32 bits

// ---------------------------------------------------------------------------
// helpers
// ---------------------------------------------------------------------------
__device__ __forceinline__ uint32_t f2tf32(float f) {
    uint32_t r;
    asm("cvt.rna.tf32.f32 %0, %1;" : "=r"(r) : "f"(f));
    return r;
}

__device__ __forceinline__ void mma_tf32(
    float& c0, float& c1, float& c2, float& c3,
    uint32_t a0, uint32_t a1, uint32_t a2, uint32_t a3,
    uint32_t b0, uint32_t b1)
{
    asm volatile(
        "mma.sync.aligned.m16n8k8.row.col.f32.tf32.tf32.f32 "
        "{%0,%1,%2,%3}, {%4,%5,%6,%7}, {%8,%9}, {%0,%1,%2,%3};\n"
        : "+f"(c0), "+f"(c1), "+f"(c2), "+f"(c3)
        : "r"(a0), "r"(a1), "r"(a2), "r"(a3), "r"(b0), "r"(b1));
}

#define LDMX4(r, addr) \
    asm volatile("ldmatrix.sync.aligned.m8n8.x4.shared.b16 {%0,%1,%2,%3}, [%4];" \
        : "=r"((r)[0]), "=r"((r)[1]), "=r"((r)[2]), "=r"((r)[3]) : "r"(addr))

__device__ __forceinline__ uint32_t sm_u32(const void* p) {
    return (uint32_t)__cvta_generic_to_shared(p);
}

__device__ __forceinline__ void cp_async16(uint32_t dst, const void* src) {
    asm volatile("cp.async.ca.shared.global [%0], [%1], 16;" :: "r"(dst), "l"(src));
}
#define CP_COMMIT() asm volatile("cp.async.commit_group;")
#define CP_WAIT1()  asm volatile("cp.async.wait_group 1;")
#define CP_WAIT0()  asm volatile("cp.async.wait_group 0;")

// ---------------------------------------------------------------------------
// Pre-pass: fp32 -> tf32 bits (elementwise), and transposing variant.
// ---------------------------------------------------------------------------
__global__ void cvt_kernel(const float* __restrict__ in, uint32_t* __restrict__ out, int n4)
{
    int i = blockIdx.x * blockDim.x + threadIdx.x;
    if (i < n4) {
        float4 v = ((const float4*)in)[i];
        ((uint4*)out)[i] = make_uint4(f2tf32(v.x), f2tf32(v.y), f2tf32(v.z), f2tf32(v.w));
    }
}

// in[R][C] -> out[C][R], tf32. grid (C/32, R/32), block (32, 8).
__global__ void transpose_cvt_kernel(const float* __restrict__ in, uint32_t* __restrict__ out,
                                     int R, int C)
{
    __shared__ uint32_t t[32][33];
    const int c = blockIdx.x * 32 + threadIdx.x;
    const int r0 = blockIdx.y * 32;
#pragma unroll
    for (int i = 0; i < 4; i++)
        t[threadIdx.y + 8 * i][threadIdx.x] = f2tf32(in[(size_t)(r0 + threadIdx.y + 8 * i) * C + c]);
    __syncthreads();
    const int oc = r0 + threadIdx.x;
    const int orow = blockIdx.x * 32 + threadIdx.y;
#pragma unroll
    for (int i = 0; i < 4; i++)
        out[(size_t)(orow + 8 * i) * R + oc] = t[threadIdx.x][threadIdx.y + 8 * i];
}

// ---------------------------------------------------------------------------
// TF32 GEMM v5: single-sync 3-stage ring.
// At iteration it (after ONE barrier): stage tile it+2 into buf (it+2)%3 ==
// (it-1)%3, which the barrier just proved everyone left. Staging issue
// overlaps the MMA block. wait_group 1 guarantees the current buffer;
// wait_group 0 on the last iteration (tail rule).
// smem: 3 stages x (A+B) x 128x36 words = 110592 B -> 2 CTAs/SM.
// ---------------------------------------------------------------------------
#define ASTR 36
#define STAGE_W (128 * ASTR)
#define NSTAGE 3

__global__ __launch_bounds__(256) void gemm_tf32_kernel(
    const uint32_t* __restrict__ A, const uint32_t* __restrict__ Bt,
    float* __restrict__ C, int M, int N, int K)
{
    extern __shared__ uint32_t sm[];
    uint32_t* As = sm;                         // [3][128][ASTR]
    uint32_t* Bs = sm + NSTAGE * STAGE_W;      // [3][128][ASTR]
    const uint32_t smA = sm_u32(As);
    const uint32_t smB = sm_u32(Bs);

    const int tid = threadIdx.x;
    const int bm = blockIdx.y * 128;
    const int bn = blockIdx.x * 128;
    const int w = tid >> 5, lane = tid & 31;
    const int wm = (w >> 2) * 64;
    const int wn = (w & 3) * 32;
    const int grp = lane >> 2;
    const int qid = lane & 3;

    const int srow = tid >> 3;
    const int sch = (tid & 7) * 4;

    const int rA = (lane & 7) + ((lane >> 3) & 1) * 8;
    const int cA = (lane >> 4) * 4;
    const int rB = (lane & 7) + ((lane >> 4) & 1) * 8;
    const int cB = ((lane >> 3) & 1) * 4;
    uint32_t aoff[4], boff[2];
#pragma unroll
    for (int mt = 0; mt < 4; mt++)
        aoff[mt] = ((wm + mt * 16 + rA) * ASTR + cA) * 4;
#pragma unroll
    for (int np = 0; np < 2; np++)
        boff[np] = ((wn + np * 16 + rB) * ASTR + cB) * 4;

    float acc[4][4][4];
#pragma unroll
    for (int mt = 0; mt < 4; mt++)
#pragma unroll
        for (int nt = 0; nt < 4; nt++)
#pragma unroll
            for (int c = 0; c < 4; c++) acc[mt][nt][c] = 0.0f;

    auto stage = [&](int buf, int k0) {
#pragma unroll
        for (int i = 0; i < 4; i++) {
            int row = srow + i * 32;
            cp_async16(smA + (buf * STAGE_W + row * ASTR + sch) * 4,
                       A + (size_t)(bm + row) * K + k0 + sch);
            cp_async16(smB + (buf * STAGE_W + row * ASTR + sch) * 4,
                       Bt + (size_t)(bn + row) * K + k0 + sch);
        }
        CP_COMMIT();
    };

    stage(0, 0);
    stage(1, 32);

    const int iters = K / 32;
    int buf = 0;          // consuming buffer
    int sbuf = 2;         // next staging buffer
    for (int it = 0; it < iters; it++) {
        if (it == iters - 1) { CP_WAIT0(); } else { CP_WAIT1(); }
        __syncthreads();

        // Stage tile it+2 (into the buffer consumed last iteration).
        if (it + 2 < iters) {
            stage(sbuf, (it + 2) * 32);
            sbuf = (sbuf == NSTAGE - 1) ? 0 : sbuf + 1;
        }

        const uint32_t baseA = smA + buf * STAGE_W * 4;
        const uint32_t baseB = smB + buf * STAGE_W * 4;
#pragma unroll
        for (int ks = 0; ks < 4; ks++) {
            uint32_t a[4][4], b[2][4];
#pragma unroll
            for (int mt = 0; mt < 4; mt++) LDMX4(a[mt], baseA + aoff[mt] + ks * 32);
#pragma unroll
            for (int np = 0; np < 2; np++) LDMX4(b[np], baseB + boff[np] + ks * 32);
#pragma unroll
            for (int mt = 0; mt < 4; mt++)
#pragma unroll
                for (int nt = 0; nt < 4; nt++)
                    mma_tf32(acc[mt][nt][0], acc[mt][nt][1], acc[mt][nt][2], acc[mt][nt][3],
                             a[mt][0], a[mt][1], a[mt][2], a[mt][3],
                             b[nt >> 1][(nt & 1) * 2], b[nt >> 1][(nt & 1) * 2 + 1]);
        }
        buf = (buf == NSTAGE - 1) ? 0 : buf + 1;
    }

#pragma unroll
    for (int mt = 0; mt < 4; mt++) {
        const int r = bm + wm + mt * 16 + grp;
#pragma unroll
        for (int nt = 0; nt < 4; nt++) {
            const int cc = bn + wn + nt * 8 + qid * 2;
            *(float2*)(C + (size_t)r * N + cc) = make_float2(acc[mt][nt][0], acc[mt][nt][1]);
            *(float2*)(C + (size_t)(r + 8) * N + cc) = make_float2(acc[mt][nt][2], acc[mt][nt][3]);
        }
    }
}

// ---------------------------------------------------------------------------
// RoPE + tf32 convert: h<20 rotates (q,k heads), h 20..23 converts v heads.
// ---------------------------------------------------------------------------
__global__ void rope_cvt_kernel(float* __restrict__ proj)
{
    const int p = blockIdx.x;
    const int h = blockIdx.y;      // 0..23
    const int j = threadIdx.x;     // 0..63

    float* row = proj + (size_t)p * QKV_DIM + h * HD;
    float x1 = row[j];
    float x2 = row[j + 64];
    if (h < NQH + NKVH) {
        float c = 1.0f, s = 0.0f;
        if (j < 32) {
            float f = exp2f(-10.0f * (float)j * (1.0f / 31.0f));
            float theta = (float)p * f;
            c = cosf(theta);
            s = sinf(theta);
        }
        float o1 = x1 * c + x2 * s;
        float o2 = -x1 * s + x2 * c;
        row[j]      = __uint_as_float(f2tf32(o1));
        row[j + 64] = __uint_as_float(f2tf32(o2));
    } else {
        row[j]      = __uint_as_float(f2tf32(x1));
        row[j + 64] = __uint_as_float(f2tf32(x2));
    }
}

// ---------------------------------------------------------------------------
// TF32 flash attention v4: v3 + cp.async K/V tile loads.
// smem: Ks[64][132] | Vs[64][136] = 68.6 KB.
// ---------------------------------------------------------------------------
#define AT_BQ 64
#define AT_BK 64
#define KS_STR 132
#define VS_STR 136
#define P_STR  68

__global__ __launch_bounds__(128) void attn_mma_kernel(
    const uint32_t* __restrict__ proj, const float* __restrict__ sink,
    uint32_t* __restrict__ out)
{
    extern __shared__ uint32_t smu[];
    uint32_t* Ks = smu;                       // 64 x KS_STR (Q staging; K; P)
    uint32_t* Vs = Ks + 64 * KS_STR;          // 64 x VS_STR
    const uint32_t smK = sm_u32(Ks);
    const uint32_t smV = sm_u32(Vs);

    const int tid  = threadIdx.x;
    const int w    = tid >> 5;
    const int lane = tid & 31;
    const int grp  = lane >> 2;
    const int qid  = lane & 3;
    const int row0 = w * 16;

    const int hq = blockIdx.y;
    const int hk = hq >> 2;
    const int q0 = blockIdx.x * AT_BQ;

    const int qoff = hq * HD;
    const int koff = NQH * HD + hk * HD;
    const int voff = (NQH + NKVH) * HD + hk * HD;

    const int rA = (lane & 7) + ((lane >> 3) & 1) * 8;
    const int cA = (lane >> 4) * 4;
    const int rB = (lane & 7) + ((lane >> 4) & 1) * 8;
    const int cB = ((lane >> 3) & 1) * 4;

    const uint32_t qbase = smK + ((row0 + rA) * KS_STR + cA) * 4;
    const uint32_t pbase = smK + ((row0 + rA) * P_STR + cA) * 4;
    uint32_t kbase[4];
#pragma unroll
    for (int np = 0; np < 4; np++)
        kbase[np] = smK + ((np * 16 + rB) * KS_STR + cB) * 4;

    // ---- Stage Q through Ks, extract resident fragments ----
    for (int n = tid; n < 64 * 32; n += 128) {
        int r = n >> 5, dv = n & 31;
        *(uint4*)(Ks + r * KS_STR + dv * 4) =
            *(const uint4*)(proj + (size_t)(q0 + r) * QKV_DIM + qoff + dv * 4);
    }
    __syncthreads();

    uint32_t qf[16][4];
#pragma unroll
    for (int ks = 0; ks < 16; ks++) LDMX4(qf[ks], qbase + ks * 32);

    const float sval = sink[hq];
    float m0 = sval, m1 = sval, l0 = 1.0f, l1 = 1.0f;
    float O[16][4];
#pragma unroll
    for (int nt = 0; nt < 16; nt++)
#pragma unroll
        for (int c = 0; c < 4; c++) O[nt][c] = 0.0f;

    const float scale = 0.08838834764831845f;
    const float NEG_INF = -__int_as_float(0x7f800000);

    for (int k0 = 0; k0 < L_SEQ; k0 += AT_BK) {
        if ((k0 + AT_BK - 1 <= q0) && (k0 > q0 + AT_BQ - 1 - WINDOW)) continue;

        __syncthreads();   // prior P/V reads (or Q frag extraction) complete

        // K + V tile loads via cp.async (16 x 16B each per thread)
        for (int n = tid; n < 64 * 32; n += 128) {
            int r = n >> 5, dv = n & 31;
            cp_async16(smK + (r * KS_STR + dv * 4) * 4,
                       proj + (size_t)(k0 + r) * QKV_DIM + koff + dv * 4);
            cp_async16(smV + (r * VS_STR + dv * 4) * 4,
                       proj + (size_t)(k0 + r) * QKV_DIM + voff + dv * 4);
        }
        CP_COMMIT();
        CP_WAIT0();
        __syncthreads();

        // ---- S = Q K^T : m16 x n64 x k128 per warp (Q resident) ----
        float S[8][4];
#pragma unroll
        for (int nt = 0; nt < 8; nt++)
#pragma unroll
            for (int c = 0; c < 4; c++) S[nt][c] = 0.0f;

#pragma unroll
        for (int ks = 0; ks < 16; ks++) {
#pragma unroll
            for (int np = 0; np < 4; np++) {
                uint32_t b[4];
                LDMX4(b, kbase[np] + ks * 32);
                mma_tf32(S[np*2][0], S[np*2][1], S[np*2][2], S[np*2][3],
                         qf[ks][0], qf[ks][1], qf[ks][2], qf[ks][3], b[0], b[1]);
                mma_tf32(S[np*2+1][0], S[np*2+1][1], S[np*2+1][2], S[np*2+1][3],
                         qf[ks][0], qf[ks][1], qf[ks][2], qf[ks][3], b[2], b[3]);
            }
        }

        // ---- mask + scale + online softmax ----
        const int qp0 = q0 + row0 + grp;
        const int qp1 = qp0 + 8;
        const bool needs_mask = !((k0 > q0 + AT_BQ - 1) ||
                                  (k0 + AT_BK - 1 + WINDOW <= q0));
        float mx0 = NEG_INF, mx1 = NEG_INF;
#pragma unroll
        for (int nt = 0; nt < 8; nt++) {
            const int kpa = k0 + nt * 8 + 2 * qid;
            const int kpb = kpa + 1;
            if (needs_mask) {
                S[nt][0] = ((kpa > qp0) || (kpa + WINDOW <= qp0)) ? S[nt][0] * scale : NEG_INF;
                S[nt][1] = ((kpb > qp0) || (kpb + WINDOW <= qp0)) ? S[nt][1] * scale : NEG_INF;
                S[nt][2] = ((kpa > qp1) || (kpa + WINDOW <= qp1)) ? S[nt][2] * scale : NEG_INF;
                S[nt][3] = ((kpb > qp1) || (kpb + WINDOW <= qp1)) ? S[nt][3] * scale : NEG_INF;
            } else {
                S[nt][0] *= scale; S[nt][1] *= scale;
                S[nt][2] *= scale; S[nt][3] *= scale;
            }
            mx0 = fmaxf(mx0, fmaxf(S[nt][0], S[nt][1]));
            mx1 = fmaxf(mx1, fmaxf(S[nt][2], S[nt][3]));
        }
        mx0 = fmaxf(mx0, __shfl_xor_sync(0xffffffffu, mx0, 1));
        mx0 = fmaxf(mx0, __shfl_xor_sync(0xffffffffu, mx0, 2));
        mx1 = fmaxf(mx1, __shfl_xor_sync(0xffffffffu, mx1, 1));
        mx1 = fmaxf(mx1, __shfl_xor_sync(0xffffffffu, mx1, 2));

        const float mn0 = fmaxf(m0, mx0);
        const float mn1 = fmaxf(m1, mx1);
        const float alpha0 = __expf(m0 - mn0);
        const float alpha1 = __expf(m1 - mn1);

        float rs0 = 0.0f, rs1 = 0.0f;
#pragma unroll
        for (int nt = 0; nt < 8; nt++) {
            S[nt][0] = __expf(S[nt][0] - mn0);
            S[nt][1] = __expf(S[nt][1] - mn0);
            S[nt][2] = __expf(S[nt][2] - mn1);
            S[nt][3] = __expf(S[nt][3] - mn1);
            rs0 += S[nt][0] + S[nt][1];
            rs1 += S[nt][2] + S[nt][3];
        }
        rs0 += __shfl_xor_sync(0xffffffffu, rs0, 1);
        rs0 += __shfl_xor_sync(0xffffffffu, rs0, 2);
        rs1 += __shfl_xor_sync(0xffffffffu, rs1, 1);
        rs1 += __shfl_xor_sync(0xffffffffu, rs1, 2);

        l0 = l0 * alpha0 + rs0;  m0 = mn0;
        l1 = l1 * alpha1 + rs1;  m1 = mn1;

#pragma unroll
        for (int nt = 0; nt < 16; nt++) {
            O[nt][0] *= alpha0; O[nt][1] *= alpha0;
            O[nt][2] *= alpha1; O[nt][3] *= alpha1;
        }

        __syncthreads();   // all warps done reading K -> overwrite as P

        uint32_t* Ps = Ks;
#pragma unroll
        for (int nt = 0; nt < 8; nt++) {
            const int cc = nt * 8 + 2 * qid;
            *(uint2*)(Ps + (row0 + grp) * P_STR + cc) =
                make_uint2(f2tf32(S[nt][0]), f2tf32(S[nt][1]));
            *(uint2*)(Ps + (row0 + grp + 8) * P_STR + cc) =
                make_uint2(f2tf32(S[nt][2]), f2tf32(S[nt][3]));
        }
        __syncwarp();

        // ---- O += P V : ldmatrix a-frags, conflict-free scalar-LDS b-frags ----
#pragma unroll
        for (int ks = 0; ks < 8; ks++) {
            const int kk = ks * 8;
            uint32_t a[4];
            LDMX4(a, pbase + ks * 32);
#pragma unroll
            for (int nt = 0; nt < 16; nt++) {
                uint32_t b0 = Vs[(kk + qid) * VS_STR + nt * 8 + grp];
                uint32_t b1 = Vs[(kk + qid + 4) * VS_STR + nt * 8 + grp];
                mma_tf32(O[nt][0], O[nt][1], O[nt][2], O[nt][3],
                         a[0], a[1], a[2], a[3], b0, b1);
            }
        }
    }

    // Epilogue: normalize, convert to tf32 bits, store
    const float inv0 = 1.0f / l0;
    const float inv1 = 1.0f / l1;
    uint32_t* dst0 = out + (size_t)(q0 + row0 + grp) * D_MODEL + hq * HD;
    uint32_t* dst1 = out + (size_t)(q0 + row0 + grp + 8) * D_MODEL + hq * HD;
#pragma unroll
    for (int nt = 0; nt < 16; nt++) {
        const int cc = nt * 8 + 2 * qid;
        *(uint2*)(dst0 + cc) = make_uint2(f2tf32(O[nt][0] * inv0), f2tf32(O[nt][1] * inv0));
        *(uint2*)(dst1 + cc) = make_uint2(f2tf32(O[nt][2] * inv1), f2tf32(O[nt][3] * inv1));
    }
}

// ---------------------------------------------------------------------------
// Launch
// ---------------------------------------------------------------------------
extern "C" void kernel_launch(void* const* d_in, const int* in_sizes, int n_in,
                              void* d_out, int out_size)
{
    const float* x    = (const float*)d_in[0];  // (1, 2048, 2048)
    const float* Wqkv = (const float*)d_in[1];  // (2048, 3072)
    const float* Wo   = (const float*)d_in[2];  // (2048, 2048)
    const float* s    = (const float*)d_in[3];  // (1, 16)
    float* out = (float*)d_out;                 // (1, 2048, 2048)

    uint32_t *xt, *wqkvt, *wot, *attn;
    float* proj;
    cudaGetSymbolAddress((void**)&xt, g_xt);
    cudaGetSymbolAddress((void**)&wqkvt, g_wqkvt);
    cudaGetSymbolAddress((void**)&wot, g_wot);
    cudaGetSymbolAddress((void**)&proj, g_proj);
    cudaGetSymbolAddress((void**)&attn, g_attn);

    // 0) Pre-pass: x -> tf32; weights -> transposed tf32
    {
        int n4 = L_SEQ * D_MODEL / 4;
        cvt_kernel<<<(n4 + 255) / 256, 256>>>(x, xt, n4);
        dim3 blk(32, 8);
        transpose_cvt_kernel<<<dim3(QKV_DIM / 32, D_MODEL / 32), blk>>>(Wqkv, wqkvt, D_MODEL, QKV_DIM);
        transpose_cvt_kernel<<<dim3(D_MODEL / 32, D_MODEL / 32), blk>>>(Wo, wot, D_MODEL, D_MODEL);
    }

    const size_t gemm_smem = 2 * NSTAGE * STAGE_W * sizeof(uint32_t);   // 110592 B
    cudaFuncSetAttribute(gemm_tf32_kernel, cudaFuncAttributeMaxDynamicSharedMemorySize, (int)gemm_smem);

    // 1) QKV projection (GEMM v5)
    {
        dim3 grid(QKV_DIM / 128, L_SEQ / 128);
        gemm_tf32_kernel<<<grid, 256, gemm_smem>>>(xt, wqkvt, proj, L_SEQ, QKV_DIM, D_MODEL);
    }

    // 2) RoPE + convert proj to tf32 bits
    {
        dim3 grid(L_SEQ, NQH + 2 * NKVH);
        rope_cvt_kernel<<<grid, 64>>>(proj);
    }

    // 3) Fused attention v4
    {
        size_t smem = (size_t)(64 * KS_STR + 64 * VS_STR) * sizeof(uint32_t);   // 68608 B
        cudaFuncSetAttribute(attn_mma_kernel, cudaFuncAttributeMaxDynamicSharedMemorySize, (int)smem);
        dim3 grid(L_SEQ / AT_BQ, NQH);
        attn_mma_kernel<<<grid, 128, smem>>>((const uint32_t*)proj, s, attn);
    }

    // 4) Output projection (GEMM v5)
    {
        dim3 grid(D_MODEL / 128, L_SEQ / 128);
        gemm_tf32_kernel<<<grid, 256, gemm_smem>>>(attn, wot, out, L_SEQ, D_MODEL, D_MODEL);
    }
}

// round 12
// speedup vs baseline: 1.0991x; 1.0991x over previous
#include <cuda_runtime.h>
#include <math.h>
#include <stdint.h>

// Problem constants
#define L_SEQ   2048
#define D_MODEL 2048
#define QKV_DIM 3072   // (16 + 2*4) * 128
#define NQH     16
#define NKVH    4
#define HD      128
#define WINDOW  1024

// Scratch (static device allocations; no cudaMalloc allowed)
__device__ uint32_t g_xt[L_SEQ * D_MODEL];        // x as tf32 bits, [m][k]
__device__ uint32_t g_wqkvt[QKV_DIM * D_MODEL];   // Wqkv^T tf32 bits, [n][k]
__device__ uint32_t g_wot[D_MODEL * D_MODEL];     // Wo^T tf32 bits, [n][k]
__device__ float    g_proj[L_SEQ * QKV_DIM];      // fp32 after GEMM; tf32 bits after rope
__device__ uint32_t g_attn[L_SEQ * D_MODEL];      // attention out, tf32 bits

// ---------------------------------------------------------------------------
// helpers
// ---------------------------------------------------------------------------
__device__ __forceinline__ uint32_t f2tf32(float f) {
    uint32_t r;
    asm("cvt.rna.tf32.f32 %0, %1;" : "=r"(r) : "f"(f));
    return r;
}

__device__ __forceinline__ void mma_tf32(
    float& c0, float& c1, float& c2, float& c3,
    uint32_t a0, uint32_t a1, uint32_t a2, uint32_t a3,
    uint32_t b0, uint32_t b1)
{
    asm volatile(
        "mma.sync.aligned.m16n8k8.row.col.f32.tf32.tf32.f32 "
        "{%0,%1,%2,%3}, {%4,%5,%6,%7}, {%8,%9}, {%0,%1,%2,%3};\n"
        : "+f"(c0), "+f"(c1), "+f"(c2), "+f"(c3)
        : "r"(a0), "r"(a1), "r"(a2), "r"(a3), "r"(b0), "r"(b1));
}

#define LDMX4(r, addr) \
    asm volatile("ldmatrix.sync.aligned.m8n8.x4.shared.b16 {%0,%1,%2,%3}, [%4];" \
        : "=r"((r)[0]), "=r"((r)[1]), "=r"((r)[2]), "=r"((r)[3]) : "r"(addr))

__device__ __forceinline__ uint32_t sm_u32(const void* p) {
    return (uint32_t)__cvta_generic_to_shared(p);
}

__device__ __forceinline__ void cp_async16(uint32_t dst, const void* src) {
    asm volatile("cp.async.ca.shared.global [%0], [%1], 16;" :: "r"(dst), "l"(src));
}
#define CP_COMMIT() asm volatile("cp.async.commit_group;")
#define CP_WAIT1()  asm volatile("cp.async.wait_group 1;")
#define CP_WAIT0()  asm volatile("cp.async.wait_group 0;")

// ---------------------------------------------------------------------------
// Pre-pass: fp32 -> tf32 bits (elementwise), and transposing variant.
// ---------------------------------------------------------------------------
__global__ void cvt_kernel(const float* __restrict__ in, uint32_t* __restrict__ out, int n4)
{
    int i = blockIdx.x * blockDim.x + threadIdx.x;
    if (i < n4) {
        float4 v = ((const float4*)in)[i];
        ((uint4*)out)[i] = make_uint4(f2tf32(v.x), f2tf32(v.y), f2tf32(v.z), f2tf32(v.w));
    }
}

// in[R][C] -> out[C][R], tf32. grid (C/32, R/32), block (32, 8).
__global__ void transpose_cvt_kernel(const float* __restrict__ in, uint32_t* __restrict__ out,
                                     int R, int C)
{
    __shared__ uint32_t t[32][33];
    const int c = blockIdx.x * 32 + threadIdx.x;
    const int r0 = blockIdx.y * 32;
#pragma unroll
    for (int i = 0; i < 4; i++)
        t[threadIdx.y + 8 * i][threadIdx.x] = f2tf32(in[(size_t)(r0 + threadIdx.y + 8 * i) * C + c]);
    __syncthreads();
    const int oc = r0 + threadIdx.x;
    const int orow = blockIdx.x * 32 + threadIdx.y;
#pragma unroll
    for (int i = 0; i < 4; i++)
        out[(size_t)(orow + 8 * i) * R + oc] = t[threadIdx.x][threadIdx.y + 8 * i];
}

// ---------------------------------------------------------------------------
// TF32 GEMM v3b (R9 known-good, local optimum of this sync structure):
// C = A(MxK) * Bt(NxK), tf32-bit inputs. 128x128 tile, BK=32, 256 threads,
// cp.async 2-stage, ldmatrix feed, wait_group 0 on the final iteration.
// ---------------------------------------------------------------------------
#define ASTR 36
#define STAGE_W (128 * ASTR)

__global__ __launch_bounds__(256) void gemm_tf32_kernel(
    const uint32_t* __restrict__ A, const uint32_t* __restrict__ Bt,
    float* __restrict__ C, int M, int N, int K)
{
    extern __shared__ uint32_t sm[];
    uint32_t* As = sm;                    // [2][128][ASTR]
    uint32_t* Bs = sm + 2 * STAGE_W;      // [2][128][ASTR]
    const uint32_t smA = sm_u32(As);
    const uint32_t smB = sm_u32(Bs);

    const int tid = threadIdx.x;
    const int bm = blockIdx.y * 128;
    const int bn = blockIdx.x * 128;
    const int w = tid >> 5, lane = tid & 31;
    const int wm = (w >> 2) * 64;
    const int wn = (w & 3) * 32;
    const int grp = lane >> 2;
    const int qid = lane & 3;

    const int srow = tid >> 3;
    const int sch = (tid & 7) * 4;

    const int rA = (lane & 7) + ((lane >> 3) & 1) * 8;
    const int cA = (lane >> 4) * 4;
    const int rB = (lane & 7) + ((lane >> 4) & 1) * 8;
    const int cB = ((lane >> 3) & 1) * 4;
    uint32_t aoff[4], boff[2];
#pragma unroll
    for (int mt = 0; mt < 4; mt++)
        aoff[mt] = ((wm + mt * 16 + rA) * ASTR + cA) * 4;
#pragma unroll
    for (int np = 0; np < 2; np++)
        boff[np] = ((wn + np * 16 + rB) * ASTR + cB) * 4;

    float acc[4][4][4];
#pragma unroll
    for (int mt = 0; mt < 4; mt++)
#pragma unroll
        for (int nt = 0; nt < 4; nt++)
#pragma unroll
            for (int c = 0; c < 4; c++) acc[mt][nt][c] = 0.0f;

    auto stage = [&](int buf, int k0) {
#pragma unroll
        for (int i = 0; i < 4; i++) {
            int row = srow + i * 32;
            cp_async16(smA + (buf * STAGE_W + row * ASTR + sch) * 4,
                       A + (size_t)(bm + row) * K + k0 + sch);
            cp_async16(smB + (buf * STAGE_W + row * ASTR + sch) * 4,
                       Bt + (size_t)(bn + row) * K + k0 + sch);
        }
        CP_COMMIT();
    };

    stage(0, 0);
    stage(1, 32);

    const int iters = K / 32;
    for (int it = 0; it < iters; it++) {
        const int buf = it & 1;
        if (it == iters - 1) { CP_WAIT0(); } else { CP_WAIT1(); }
        __syncthreads();

        const uint32_t baseA = smA + buf * STAGE_W * 4;
        const uint32_t baseB = smB + buf * STAGE_W * 4;
#pragma unroll
        for (int ks = 0; ks < 4; ks++) {
            uint32_t a[4][4], b[2][4];
#pragma unroll
            for (int mt = 0; mt < 4; mt++) LDMX4(a[mt], baseA + aoff[mt] + ks * 32);
#pragma unroll
            for (int np = 0; np < 2; np++) LDMX4(b[np], baseB + boff[np] + ks * 32);
#pragma unroll
            for (int mt = 0; mt < 4; mt++)
#pragma unroll
                for (int nt = 0; nt < 4; nt++)
                    mma_tf32(acc[mt][nt][0], acc[mt][nt][1], acc[mt][nt][2], acc[mt][nt][3],
                             a[mt][0], a[mt][1], a[mt][2], a[mt][3],
                             b[nt >> 1][(nt & 1) * 2], b[nt >> 1][(nt & 1) * 2 + 1]);
        }
        __syncthreads();
        if ((it + 2) < iters) stage(buf, (it + 2) * 32);
    }

#pragma unroll
    for (int mt = 0; mt < 4; mt++) {
        const int r = bm + wm + mt * 16 + grp;
#pragma unroll
        for (int nt = 0; nt < 4; nt++) {
            const int cc = bn + wn + nt * 8 + qid * 2;
            *(float2*)(C + (size_t)r * N + cc) = make_float2(acc[mt][nt][0], acc[mt][nt][1]);
            *(float2*)(C + (size_t)(r + 8) * N + cc) = make_float2(acc[mt][nt][2], acc[mt][nt][3]);
        }
    }
}

// ---------------------------------------------------------------------------
// RoPE + tf32 convert: h<20 rotates (q,k heads), h 20..23 converts v heads.
// ---------------------------------------------------------------------------
__global__ void rope_cvt_kernel(float* __restrict__ proj)
{
    const int p = blockIdx.x;
    const int h = blockIdx.y;      // 0..23
    const int j = threadIdx.x;     // 0..63

    float* row = proj + (size_t)p * QKV_DIM + h * HD;
    float x1 = row[j];
    float x2 = row[j + 64];
    if (h < NQH + NKVH) {
        float c = 1.0f, s = 0.0f;
        if (j < 32) {
            float f = exp2f(-10.0f * (float)j * (1.0f / 31.0f));
            float theta = (float)p * f;
            c = cosf(theta);
            s = sinf(theta);
        }
        float o1 = x1 * c + x2 * s;
        float o2 = -x1 * s + x2 * c;
        row[j]      = __uint_as_float(f2tf32(o1));
        row[j + 64] = __uint_as_float(f2tf32(o2));
    } else {
        row[j]      = __uint_as_float(f2tf32(x1));
        row[j + 64] = __uint_as_float(f2tf32(x2));
    }
}

// ---------------------------------------------------------------------------
// TF32 flash attention v4 (R11 winner): Q-resident frags, cp.async K/V loads,
// ldmatrix K b-frags + P a-frags, conflict-free scalar-LDS V b-frags.
// smem: Ks[64][132] | Vs[64][136] = 68.6 KB.
// ---------------------------------------------------------------------------
#define AT_BQ 64
#define AT_BK 64
#define KS_STR 132
#define VS_STR 136
#define P_STR  68

__global__ __launch_bounds__(128) void attn_mma_kernel(
    const uint32_t* __restrict__ proj, const float* __restrict__ sink,
    uint32_t* __restrict__ out)
{
    extern __shared__ uint32_t smu[];
    uint32_t* Ks = smu;                       // 64 x KS_STR (Q staging; K; P)
    uint32_t* Vs = Ks + 64 * KS_STR;          // 64 x VS_STR
    const uint32_t smK = sm_u32(Ks);
    const uint32_t smV = sm_u32(Vs);

    const int tid  = threadIdx.x;
    const int w    = tid >> 5;
    const int lane = tid & 31;
    const int grp  = lane >> 2;
    const int qid  = lane & 3;
    const int row0 = w * 16;

    const int hq = blockIdx.y;
    const int hk = hq >> 2;
    const int q0 = blockIdx.x * AT_BQ;

    const int qoff = hq * HD;
    const int koff = NQH * HD + hk * HD;
    const int voff = (NQH + NKVH) * HD + hk * HD;

    const int rA = (lane & 7) + ((lane >> 3) & 1) * 8;
    const int cA = (lane >> 4) * 4;
    const int rB = (lane & 7) + ((lane >> 4) & 1) * 8;
    const int cB = ((lane >> 3) & 1) * 4;

    const uint32_t qbase = smK + ((row0 + rA) * KS_STR + cA) * 4;
    const uint32_t pbase = smK + ((row0 + rA) * P_STR + cA) * 4;
    uint32_t kbase[4];
#pragma unroll
    for (int np = 0; np < 4; np++)
        kbase[np] = smK + ((np * 16 + rB) * KS_STR + cB) * 4;

    // ---- Stage Q through Ks, extract resident fragments ----
    for (int n = tid; n < 64 * 32; n += 128) {
        int r = n >> 5, dv = n & 31;
        *(uint4*)(Ks + r * KS_STR + dv * 4) =
            *(const uint4*)(proj + (size_t)(q0 + r) * QKV_DIM + qoff + dv * 4);
    }
    __syncthreads();

    uint32_t qf[16][4];
#pragma unroll
    for (int ks = 0; ks < 16; ks++) LDMX4(qf[ks], qbase + ks * 32);

    const float sval = sink[hq];
    float m0 = sval, m1 = sval, l0 = 1.0f, l1 = 1.0f;
    float O[16][4];
#pragma unroll
    for (int nt = 0; nt < 16; nt++)
#pragma unroll
        for (int c = 0; c < 4; c++) O[nt][c] = 0.0f;

    const float scale = 0.08838834764831845f;
    const float NEG_INF = -__int_as_float(0x7f800000);

    for (int k0 = 0; k0 < L_SEQ; k0 += AT_BK) {
        if ((k0 + AT_BK - 1 <= q0) && (k0 > q0 + AT_BQ - 1 - WINDOW)) continue;

        __syncthreads();   // prior P/V reads (or Q frag extraction) complete

        // K + V tile loads via cp.async (16 x 16B each per thread)
        for (int n = tid; n < 64 * 32; n += 128) {
            int r = n >> 5, dv = n & 31;
            cp_async16(smK + (r * KS_STR + dv * 4) * 4,
                       proj + (size_t)(k0 + r) * QKV_DIM + koff + dv * 4);
            cp_async16(smV + (r * VS_STR + dv * 4) * 4,
                       proj + (size_t)(k0 + r) * QKV_DIM + voff + dv * 4);
        }
        CP_COMMIT();
        CP_WAIT0();
        __syncthreads();

        // ---- S = Q K^T : m16 x n64 x k128 per warp (Q resident) ----
        float S[8][4];
#pragma unroll
        for (int nt = 0; nt < 8; nt++)
#pragma unroll
            for (int c = 0; c < 4; c++) S[nt][c] = 0.0f;

#pragma unroll
        for (int ks = 0; ks < 16; ks++) {
#pragma unroll
            for (int np = 0; np < 4; np++) {
                uint32_t b[4];
                LDMX4(b, kbase[np] + ks * 32);
                mma_tf32(S[np*2][0], S[np*2][1], S[np*2][2], S[np*2][3],
                         qf[ks][0], qf[ks][1], qf[ks][2], qf[ks][3], b[0], b[1]);
                mma_tf32(S[np*2+1][0], S[np*2+1][1], S[np*2+1][2], S[np*2+1][3],
                         qf[ks][0], qf[ks][1], qf[ks][2], qf[ks][3], b[2], b[3]);
            }
        }

        // ---- mask + scale + online softmax ----
        const int qp0 = q0 + row0 + grp;
        const int qp1 = qp0 + 8;
        const bool needs_mask = !((k0 > q0 + AT_BQ - 1) ||
                                  (k0 + AT_BK - 1 + WINDOW <= q0));
        float mx0 = NEG_INF, mx1 = NEG_INF;
#pragma unroll
        for (int nt = 0; nt < 8; nt++) {
            const int kpa = k0 + nt * 8 + 2 * qid;
            const int kpb = kpa + 1;
            if (needs_mask) {
                S[nt][0] = ((kpa > qp0) || (kpa + WINDOW <= qp0)) ? S[nt][0] * scale : NEG_INF;
                S[nt][1] = ((kpb > qp0) || (kpb + WINDOW <= qp0)) ? S[nt][1] * scale : NEG_INF;
                S[nt][2] = ((kpa > qp1) || (kpa + WINDOW <= qp1)) ? S[nt][2] * scale : NEG_INF;
                S[nt][3] = ((kpb > qp1) || (kpb + WINDOW <= qp1)) ? S[nt][3] * scale : NEG_INF;
            } else {
                S[nt][0] *= scale; S[nt][1] *= scale;
                S[nt][2] *= scale; S[nt][3] *= scale;
            }
            mx0 = fmaxf(mx0, fmaxf(S[nt][0], S[nt][1]));
            mx1 = fmaxf(mx1, fmaxf(S[nt][2], S[nt][3]));
        }
        mx0 = fmaxf(mx0, __shfl_xor_sync(0xffffffffu, mx0, 1));
        mx0 = fmaxf(mx0, __shfl_xor_sync(0xffffffffu, mx0, 2));
        mx1 = fmaxf(mx1, __shfl_xor_sync(0xffffffffu, mx1, 1));
        mx1 = fmaxf(mx1, __shfl_xor_sync(0xffffffffu, mx1, 2));

        const float mn0 = fmaxf(m0, mx0);
        const float mn1 = fmaxf(m1, mx1);
        const float alpha0 = __expf(m0 - mn0);
        const float alpha1 = __expf(m1 - mn1);

        float rs0 = 0.0f, rs1 = 0.0f;
#pragma unroll
        for (int nt = 0; nt < 8; nt++) {
            S[nt][0] = __expf(S[nt][0] - mn0);
            S[nt][1] = __expf(S[nt][1] - mn0);
            S[nt][2] = __expf(S[nt][2] - mn1);
            S[nt][3] = __expf(S[nt][3] - mn1);
            rs0 += S[nt][0] + S[nt][1];
            rs1 += S[nt][2] + S[nt][3];
        }
        rs0 += __shfl_xor_sync(0xffffffffu, rs0, 1);
        rs0 += __shfl_xor_sync(0xffffffffu, rs0, 2);
        rs1 += __shfl_xor_sync(0xffffffffu, rs1, 1);
        rs1 += __shfl_xor_sync(0xffffffffu, rs1, 2);

        l0 = l0 * alpha0 + rs0;  m0 = mn0;
        l1 = l1 * alpha1 + rs1;  m1 = mn1;

#pragma unroll
        for (int nt = 0; nt < 16; nt++) {
            O[nt][0] *= alpha0; O[nt][1] *= alpha0;
            O[nt][2] *= alpha1; O[nt][3] *= alpha1;
        }

        __syncthreads();   // all warps done reading K -> overwrite as P

        uint32_t* Ps = Ks;
#pragma unroll
        for (int nt = 0; nt < 8; nt++) {
            const int cc = nt * 8 + 2 * qid;
            *(uint2*)(Ps + (row0 + grp) * P_STR + cc) =
                make_uint2(f2tf32(S[nt][0]), f2tf32(S[nt][1]));
            *(uint2*)(Ps + (row0 + grp + 8) * P_STR + cc) =
                make_uint2(f2tf32(S[nt][2]), f2tf32(S[nt][3]));
        }
        __syncwarp();

        // ---- O += P V : ldmatrix a-frags, conflict-free scalar-LDS b-frags ----
#pragma unroll
        for (int ks = 0; ks < 8; ks++) {
            const int kk = ks * 8;
            uint32_t a[4];
            LDMX4(a, pbase + ks * 32);
#pragma unroll
            for (int nt = 0; nt < 16; nt++) {
                uint32_t b0 = Vs[(kk + qid) * VS_STR + nt * 8 + grp];
                uint32_t b1 = Vs[(kk + qid + 4) * VS_STR + nt * 8 + grp];
                mma_tf32(O[nt][0], O[nt][1], O[nt][2], O[nt][3],
                         a[0], a[1], a[2], a[3], b0, b1);
            }
        }
    }

    // Epilogue: normalize, convert to tf32 bits, store
    const float inv0 = 1.0f / l0;
    const float inv1 = 1.0f / l1;
    uint32_t* dst0 = out + (size_t)(q0 + row0 + grp) * D_MODEL + hq * HD;
    uint32_t* dst1 = out + (size_t)(q0 + row0 + grp + 8) * D_MODEL + hq * HD;
#pragma unroll
    for (int nt = 0; nt < 16; nt++) {
        const int cc = nt * 8 + 2 * qid;
        *(uint2*)(dst0 + cc) = make_uint2(f2tf32(O[nt][0] * inv0), f2tf32(O[nt][1] * inv0));
        *(uint2*)(dst1 + cc) = make_uint2(f2tf32(O[nt][2] * inv1), f2tf32(O[nt][3] * inv1));
    }
}

// ---------------------------------------------------------------------------
// Launch
// ---------------------------------------------------------------------------
extern "C" void kernel_launch(void* const* d_in, const int* in_sizes, int n_in,
                              void* d_out, int out_size)
{
    const float* x    = (const float*)d_in[0];  // (1, 2048, 2048)
    const float* Wqkv = (const float*)d_in[1];  // (2048, 3072)
    const float* Wo   = (const float*)d_in[2];  // (2048, 2048)
    const float* s    = (const float*)d_in[3];  // (1, 16)
    float* out = (float*)d_out;                 // (1, 2048, 2048)

    uint32_t *xt, *wqkvt, *wot, *attn;
    float* proj;
    cudaGetSymbolAddress((void**)&xt, g_xt);
    cudaGetSymbolAddress((void**)&wqkvt, g_wqkvt);
    cudaGetSymbolAddress((void**)&wot, g_wot);
    cudaGetSymbolAddress((void**)&proj, g_proj);
    cudaGetSymbolAddress((void**)&attn, g_attn);

    // 0) Pre-pass: x -> tf32; weights -> transposed tf32
    {
        int n4 = L_SEQ * D_MODEL / 4;
        cvt_kernel<<<(n4 + 255) / 256, 256>>>(x, xt, n4);
        dim3 blk(32, 8);
        transpose_cvt_kernel<<<dim3(QKV_DIM / 32, D_MODEL / 32), blk>>>(Wqkv, wqkvt, D_MODEL, QKV_DIM);
        transpose_cvt_kernel<<<dim3(D_MODEL / 32, D_MODEL / 32), blk>>>(Wo, wot, D_MODEL, D_MODEL);
    }

    const size_t gemm_smem = 4 * STAGE_W * sizeof(uint32_t);   // 73728 B
    cudaFuncSetAttribute(gemm_tf32_kernel, cudaFuncAttributeMaxDynamicSharedMemorySize, (int)gemm_smem);

    // 1) QKV projection (GEMM v3b, 2-stage)
    {
        dim3 grid(QKV_DIM / 128, L_SEQ / 128);
        gemm_tf32_kernel<<<grid, 256, gemm_smem>>>(xt, wqkvt, proj, L_SEQ, QKV_DIM, D_MODEL);
    }

    // 2) RoPE + convert proj to tf32 bits
    {
        dim3 grid(L_SEQ, NQH + 2 * NKVH);
        rope_cvt_kernel<<<grid, 64>>>(proj);
    }

    // 3) Fused attention v4 (cp.async loads)
    {
        size_t smem = (size_t)(64 * KS_STR + 64 * VS_STR) * sizeof(uint32_t);   // 68608 B
        cudaFuncSetAttribute(attn_mma_kernel, cudaFuncAttributeMaxDynamicSharedMemorySize, (int)smem);
        dim3 grid(L_SEQ / AT_BQ, NQH);
        attn_mma_kernel<<<grid, 128, smem>>>((const uint32_t*)proj, s, attn);
    }

    // 4) Output projection (GEMM v3b, 2-stage)
    {
        dim3 grid(D_MODEL / 128, L_SEQ / 128);
        gemm_tf32_kernel<<<grid, 256, gemm_smem>>>(attn, wot, out, L_SEQ, D_MODEL, D_MODEL);
    }
}

// round 14
// speedup vs baseline: 1.7432x; 1.5861x over previous
#include <cuda_runtime.h>
#include <cuda_fp16.h>
#include <math.h>
#include <stdint.h>

// Problem constants
#define L_SEQ   2048
#define D_MODEL 2048
#define QKV_DIM 3072   // (16 + 2*4) * 128
#define NQH     16
#define NKVH    4
#define HD      128
#define WINDOW  1024

// Scratch (static device allocations; no cudaMalloc allowed)
__device__ __half g_xh[L_SEQ * D_MODEL];        // x fp16, [m][k]
__device__ __half g_wqkvth[QKV_DIM * D_MODEL];  // Wqkv^T fp16, [n][k]
__device__ __half g_woth[D_MODEL * D_MODEL];    // Wo^T fp16, [n][k]
__device__ float  g_proj[L_SEQ * QKV_DIM];      // QKV GEMM out, fp32
__device__ __half g_projh[L_SEQ * QKV_DIM];     // after rope, fp16
__device__ __half g_attnh[L_SEQ * D_MODEL];     // attention out, fp16

// ---------------------------------------------------------------------------
// helpers
// ---------------------------------------------------------------------------
__device__ __forceinline__ uint32_t pack_h2(float a, float b) {
    __half2 h = __floats2half2_rn(a, b);
    return *(uint32_t*)&h;
}

__device__ __forceinline__ void mma_f16(
    float& c0, float& c1, float& c2, float& c3,
    uint32_t a0, uint32_t a1, uint32_t a2, uint32_t a3,
    uint32_t b0, uint32_t b1)
{
    asm volatile(
        "mma.sync.aligned.m16n8k16.row.col.f32.f16.f16.f32 "
        "{%0,%1,%2,%3}, {%4,%5,%6,%7}, {%8,%9}, {%0,%1,%2,%3};\n"
        : "+f"(c0), "+f"(c1), "+f"(c2), "+f"(c3)
        : "r"(a0), "r"(a1), "r"(a2), "r"(a3), "r"(b0), "r"(b1));
}

#define LDMX4(r, addr) \
    asm volatile("ldmatrix.sync.aligned.m8n8.x4.shared.b16 {%0,%1,%2,%3}, [%4];" \
        : "=r"((r)[0]), "=r"((r)[1]), "=r"((r)[2]), "=r"((r)[3]) : "r"(addr))

#define LDMX4T(r, addr) \
    asm volatile("ldmatrix.sync.aligned.m8n8.x4.trans.shared.b16 {%0,%1,%2,%3}, [%4];" \
        : "=r"((r)[0]), "=r"((r)[1]), "=r"((r)[2]), "=r"((r)[3]) : "r"(addr))

__device__ __forceinline__ uint32_t sm_u32(const void* p) {
    return (uint32_t)__cvta_generic_to_shared(p);
}

__device__ __forceinline__ void cp_async16(uint32_t dst, const void* src) {
    asm volatile("cp.async.ca.shared.global [%0], [%1], 16;" :: "r"(dst), "l"(src));
}
#define CP_COMMIT() asm volatile("cp.async.commit_group;")
#define CP_WAIT1()  asm volatile("cp.async.wait_group 1;")
#define CP_WAIT0()  asm volatile("cp.async.wait_group 0;")

// ---------------------------------------------------------------------------
// Pre-pass: fp32 -> fp16, elementwise and transposing.
// ---------------------------------------------------------------------------
__global__ void cvt_h_kernel(const float* __restrict__ in, __half* __restrict__ out, int n4)
{
    int i = blockIdx.x * blockDim.x + threadIdx.x;
    if (i < n4) {
        float4 v = ((const float4*)in)[i];
        uint2 o;
        o.x = pack_h2(v.x, v.y);
        o.y = pack_h2(v.z, v.w);
        ((uint2*)out)[i] = o;
    }
}

// in[R][C] fp32 -> out[C][R] fp16. grid (C/32, R/32), block (32, 8).
__global__ void transpose_cvt_h_kernel(const float* __restrict__ in, __half* __restrict__ out,
                                       int R, int C)
{
    __shared__ __half t[32][33];
    const int c = blockIdx.x * 32 + threadIdx.x;
    const int r0 = blockIdx.y * 32;
#pragma unroll
    for (int i = 0; i < 4; i++)
        t[threadIdx.y + 8 * i][threadIdx.x] =
            __float2half_rn(in[(size_t)(r0 + threadIdx.y + 8 * i) * C + c]);
    __syncthreads();
    const int oc = r0 + threadIdx.x;
    const int orow = blockIdx.x * 32 + threadIdx.y;
#pragma unroll
    for (int i = 0; i < 4; i++)
        out[(size_t)(orow + 8 * i) * R + oc] = t[threadIdx.x][threadIdx.y + 8 * i];
}

// ---------------------------------------------------------------------------
// FP16 GEMM (v3b skeleton): C(MxN fp32) = A(MxK fp16) * Bt(NxK fp16).
// 128x128 tile, BK=32, 256 threads, cp.async 2-stage, ldmatrix feed,
// m16n8k16 MMA (2 ksteps of 16 per BK).
// smem row stride: 40 fp16 = 80 bytes (data 64B + 16B pad; conflict-free).
// ---------------------------------------------------------------------------
#define HSTR 40                    // fp16 per smem row
#define HSTR_B (HSTR * 2)          // bytes
#define HSTAGE (128 * HSTR)        // fp16 per stage buffer

__global__ __launch_bounds__(256) void gemm_f16_kernel(
    const __half* __restrict__ A, const __half* __restrict__ Bt,
    float* __restrict__ C, int M, int N, int K)
{
    extern __shared__ __half smh[];
    __half* As = smh;                    // [2][128][HSTR]
    __half* Bs = smh + 2 * HSTAGE;       // [2][128][HSTR]
    const uint32_t smA = sm_u32(As);
    const uint32_t smB = sm_u32(Bs);

    const int tid = threadIdx.x;
    const int bm = blockIdx.y * 128;
    const int bn = blockIdx.x * 128;
    const int w = tid >> 5, lane = tid & 31;
    const int wm = (w >> 2) * 64;
    const int wn = (w & 3) * 32;
    const int grp = lane >> 2;
    const int qid = lane & 3;

    // staging: 512 chunks (128 rows x 4 x 16B) per tile, 2 per thread
    const int srow = tid >> 2;            // 0..63 (+64)
    const int sch = (tid & 3) * 16;       // byte chunk in row (0,16,32,48)

    // ldmatrix lane offsets
    const int rA16 = lane & 15;                                  // A/P row
    const int cA16 = (lane >> 4) * 16;                           // byte col
    const int rBn = (lane & 7) + ((lane >> 4) & 1) * 8;          // B n-row
    const int cBk = ((lane >> 3) & 1) * 16;                      // byte k col

    uint32_t aoff[4], boff[2];
#pragma unroll
    for (int mt = 0; mt < 4; mt++)
        aoff[mt] = (wm + mt * 16 + rA16) * HSTR_B + cA16;
#pragma unroll
    for (int np = 0; np < 2; np++)
        boff[np] = (wn + np * 16 + rBn) * HSTR_B + cBk;

    float acc[4][4][4];
#pragma unroll
    for (int mt = 0; mt < 4; mt++)
#pragma unroll
        for (int nt = 0; nt < 4; nt++)
#pragma unroll
            for (int c = 0; c < 4; c++) acc[mt][nt][c] = 0.0f;

    auto stage = [&](int buf, int k0) {
#pragma unroll
        for (int i = 0; i < 2; i++) {
            int row = srow + i * 64;
            cp_async16(smA + buf * HSTAGE * 2 + row * HSTR_B + sch,
                       A + (size_t)(bm + row) * K + k0 + sch / 2);
            cp_async16(smB + buf * HSTAGE * 2 + row * HSTR_B + sch,
                       Bt + (size_t)(bn + row) * K + k0 + sch / 2);
        }
        CP_COMMIT();
    };

    stage(0, 0);
    stage(1, 32);

    const int iters = K / 32;
    for (int it = 0; it < iters; it++) {
        const int buf = it & 1;
        if (it == iters - 1) { CP_WAIT0(); } else { CP_WAIT1(); }
        __syncthreads();

        const uint32_t baseA = smA + buf * HSTAGE * 2;
        const uint32_t baseB = smB + buf * HSTAGE * 2;
#pragma unroll
        for (int ks = 0; ks < 2; ks++) {          // 2 ksteps of 16
            uint32_t a[4][4], b[2][4];
#pragma unroll
            for (int mt = 0; mt < 4; mt++) LDMX4(a[mt], baseA + aoff[mt] + ks * 32);
#pragma unroll
            for (int np = 0; np < 2; np++) LDMX4(b[np], baseB + boff[np] + ks * 32);
#pragma unroll
            for (int mt = 0; mt < 4; mt++)
#pragma unroll
                for (int nt = 0; nt < 4; nt++)
                    mma_f16(acc[mt][nt][0], acc[mt][nt][1], acc[mt][nt][2], acc[mt][nt][3],
                            a[mt][0], a[mt][1], a[mt][2], a[mt][3],
                            b[nt >> 1][(nt & 1) * 2], b[nt >> 1][(nt & 1) * 2 + 1]);
        }
        __syncthreads();
        if ((it + 2) < iters) stage(buf, (it + 2) * 32);
    }

#pragma unroll
    for (int mt = 0; mt < 4; mt++) {
        const int r = bm + wm + mt * 16 + grp;
#pragma unroll
        for (int nt = 0; nt < 4; nt++) {
            const int cc = bn + wn + nt * 8 + qid * 2;
            *(float2*)(C + (size_t)r * N + cc) = make_float2(acc[mt][nt][0], acc[mt][nt][1]);
            *(float2*)(C + (size_t)(r + 8) * N + cc) = make_float2(acc[mt][nt][2], acc[mt][nt][3]);
        }
    }
}

// ---------------------------------------------------------------------------
// RoPE + fp16 convert: fp32 g_proj -> fp16 g_projh. h<20 rotates, rest copies.
// ---------------------------------------------------------------------------
__global__ void rope_cvt_h_kernel(const float* __restrict__ proj, __half* __restrict__ projh)
{
    const int p = blockIdx.x;
    const int h = blockIdx.y;      // 0..23
    const int j = threadIdx.x;     // 0..63

    const float* row = proj + (size_t)p * QKV_DIM + h * HD;
    __half* orow = projh + (size_t)p * QKV_DIM + h * HD;
    float x1 = row[j];
    float x2 = row[j + 64];
    if (h < NQH + NKVH) {
        float c = 1.0f, s = 0.0f;
        if (j < 32) {
            float f = exp2f(-10.0f * (float)j * (1.0f / 31.0f));
            float theta = (float)p * f;
            c = cosf(theta);
            s = sinf(theta);
        }
        orow[j]      = __float2half_rn(x1 * c + x2 * s);
        orow[j + 64] = __float2half_rn(-x1 * s + x2 * c);
    } else {
        orow[j]      = __float2half_rn(x1);
        orow[j + 64] = __float2half_rn(x2);
    }
}

// ---------------------------------------------------------------------------
// FP16 flash attention (v4 skeleton): Q-resident frags, cp.async K/V loads,
// ldmatrix K b-frags, ldmatrix P a-frags, ldmatrix.trans V b-frags.
// smem: Ks[64][136] fp16 (Q stage; K; P stride 72) | Vs[64][136] = 34816 B.
// ---------------------------------------------------------------------------
#define AT_BQ 64
#define AT_BK 64
#define AKS 136                 // fp16 row stride for Q/K/V (272 B)
#define AKS_B (AKS * 2)
#define APS 72                  // fp16 row stride for P (144 B)
#define APS_B (APS * 2)

__global__ __launch_bounds__(128) void attn_f16_kernel(
    const __half* __restrict__ proj, const float* __restrict__ sink,
    __half* __restrict__ out)
{
    extern __shared__ __half smh[];
    __half* Ks = smh;                       // 64 x AKS (Q staging; K; P)
    __half* Vs = smh + 64 * AKS;            // 64 x AKS
    const uint32_t smK = sm_u32(Ks);
    const uint32_t smV = sm_u32(Vs);

    const int tid  = threadIdx.x;
    const int w    = tid >> 5;
    const int lane = tid & 31;
    const int grp  = lane >> 2;
    const int qid  = lane & 3;
    const int row0 = w * 16;

    const int hq = blockIdx.y;
    const int hk = hq >> 2;
    const int q0 = blockIdx.x * AT_BQ;

    const int qoff = hq * HD;
    const int koff = NQH * HD + hk * HD;
    const int voff = (NQH + NKVH) * HD + hk * HD;

    // ldmatrix lane offsets
    const int rA16 = lane & 15;                              // A-pattern row
    const int cA16 = (lane >> 4) * 16;                       // A-pattern byte col
    const int rBn = (lane & 7) + ((lane >> 4) & 1) * 8;      // B n-row
    const int cBk = ((lane >> 3) & 1) * 16;                  // B byte k col
    const int rV  = (lane & 7) + ((lane >> 3) & 1) * 8;      // V trans k-row
    const int cV  = (lane >> 4) * 16;                        // V trans byte d col

    const uint32_t qbase = smK + (row0 + rA16) * AKS_B + cA16;
    const uint32_t pbase = smK + (row0 + rA16) * APS_B + cA16;
    uint32_t kbase[4], vbase[8];
#pragma unroll
    for (int np = 0; np < 4; np++)
        kbase[np] = smK + (np * 16 + rBn) * AKS_B + cBk;
#pragma unroll
    for (int np = 0; np < 8; np++)
        vbase[np] = smV + rV * AKS_B + np * 32 + cV;

    // ---- Stage Q through Ks, extract resident fragments ----
    for (int c = tid; c < 1024; c += 128) {
        int r = c >> 4, ch = c & 15;
        cp_async16(smK + r * AKS_B + ch * 16,
                   proj + (size_t)(q0 + r) * QKV_DIM + qoff + ch * 8);
    }
    CP_COMMIT();
    CP_WAIT0();
    __syncthreads();

    uint32_t qf[8][4];
#pragma unroll
    for (int ks = 0; ks < 8; ks++) LDMX4(qf[ks], qbase + ks * 32);

    const float sval = sink[hq];
    float m0 = sval, m1 = sval, l0 = 1.0f, l1 = 1.0f;
    float O[16][4];
#pragma unroll
    for (int nt = 0; nt < 16; nt++)
#pragma unroll
        for (int c = 0; c < 4; c++) O[nt][c] = 0.0f;

    const float scale = 0.08838834764831845f;
    const float NEG_INF = -__int_as_float(0x7f800000);

    for (int k0 = 0; k0 < L_SEQ; k0 += AT_BK) {
        if ((k0 + AT_BK - 1 <= q0) && (k0 > q0 + AT_BQ - 1 - WINDOW)) continue;

        __syncthreads();   // prior P/V reads (or Q frag extraction) complete

        // K + V tile loads via cp.async (8 + 8 x 16B per thread)
        for (int c = tid; c < 1024; c += 128) {
            int r = c >> 4, ch = c & 15;
            cp_async16(smK + r * AKS_B + ch * 16,
                       proj + (size_t)(k0 + r) * QKV_DIM + koff + ch * 8);
            cp_async16(smV + r * AKS_B + ch * 16,
                       proj + (size_t)(k0 + r) * QKV_DIM + voff + ch * 8);
        }
        CP_COMMIT();
        CP_WAIT0();
        __syncthreads();

        // ---- S = Q K^T : m16 x n64 x k128 per warp (Q resident) ----
        float S[8][4];
#pragma unroll
        for (int nt = 0; nt < 8; nt++)
#pragma unroll
            for (int c = 0; c < 4; c++) S[nt][c] = 0.0f;

#pragma unroll
        for (int ks = 0; ks < 8; ks++) {
#pragma unroll
            for (int np = 0; np < 4; np++) {
                uint32_t b[4];
                LDMX4(b, kbase[np] + ks * 32);
                mma_f16(S[np*2][0], S[np*2][1], S[np*2][2], S[np*2][3],
                        qf[ks][0], qf[ks][1], qf[ks][2], qf[ks][3], b[0], b[1]);
                mma_f16(S[np*2+1][0], S[np*2+1][1], S[np*2+1][2], S[np*2+1][3],
                        qf[ks][0], qf[ks][1], qf[ks][2], qf[ks][3], b[2], b[3]);
            }
        }

        // ---- mask + scale + online softmax ----
        const int qp0 = q0 + row0 + grp;
        const int qp1 = qp0 + 8;
        const bool needs_mask = !((k0 > q0 + AT_BQ - 1) ||
                                  (k0 + AT_BK - 1 + WINDOW <= q0));
        float mx0 = NEG_INF, mx1 = NEG_INF;
#pragma unroll
        for (int nt = 0; nt < 8; nt++) {
            const int kpa = k0 + nt * 8 + 2 * qid;
            const int kpb = kpa + 1;
            if (needs_mask) {
                S[nt][0] = ((kpa > qp0) || (kpa + WINDOW <= qp0)) ? S[nt][0] * scale : NEG_INF;
                S[nt][1] = ((kpb > qp0) || (kpb + WINDOW <= qp0)) ? S[nt][1] * scale : NEG_INF;
                S[nt][2] = ((kpa > qp1) || (kpa + WINDOW <= qp1)) ? S[nt][2] * scale : NEG_INF;
                S[nt][3] = ((kpb > qp1) || (kpb + WINDOW <= qp1)) ? S[nt][3] * scale : NEG_INF;
            } else {
                S[nt][0] *= scale; S[nt][1] *= scale;
                S[nt][2] *= scale; S[nt][3] *= scale;
            }
            mx0 = fmaxf(mx0, fmaxf(S[nt][0], S[nt][1]));
            mx1 = fmaxf(mx1, fmaxf(S[nt][2], S[nt][3]));
        }
        mx0 = fmaxf(mx0, __shfl_xor_sync(0xffffffffu, mx0, 1));
        mx0 = fmaxf(mx0, __shfl_xor_sync(0xffffffffu, mx0, 2));
        mx1 = fmaxf(mx1, __shfl_xor_sync(0xffffffffu, mx1, 1));
        mx1 = fmaxf(mx1, __shfl_xor_sync(0xffffffffu, mx1, 2));

        const float mn0 = fmaxf(m0, mx0);
        const float mn1 = fmaxf(m1, mx1);
        const float alpha0 = __expf(m0 - mn0);
        const float alpha1 = __expf(m1 - mn1);

        float rs0 = 0.0f, rs1 = 0.0f;
#pragma unroll
        for (int nt = 0; nt < 8; nt++) {
            S[nt][0] = __expf(S[nt][0] - mn0);
            S[nt][1] = __expf(S[nt][1] - mn0);
            S[nt][2] = __expf(S[nt][2] - mn1);
            S[nt][3] = __expf(S[nt][3] - mn1);
            rs0 += S[nt][0] + S[nt][1];
            rs1 += S[nt][2] + S[nt][3];
        }
        rs0 += __shfl_xor_sync(0xffffffffu, rs0, 1);
        rs0 += __shfl_xor_sync(0xffffffffu, rs0, 2);
        rs1 += __shfl_xor_sync(0xffffffffu, rs1, 1);
        rs1 += __shfl_xor_sync(0xffffffffu, rs1, 2);

        l0 = l0 * alpha0 + rs0;  m0 = mn0;
        l1 = l1 * alpha1 + rs1;  m1 = mn1;

#pragma unroll
        for (int nt = 0; nt < 16; nt++) {
            O[nt][0] *= alpha0; O[nt][1] *= alpha0;
            O[nt][2] *= alpha1; O[nt][3] *= alpha1;
        }

        __syncthreads();   // all warps done reading K -> overwrite as P

        __half* Ps = Ks;
#pragma unroll
        for (int nt = 0; nt < 8; nt++) {
            const int cc = nt * 8 + 2 * qid;
            *(uint32_t*)&Ps[(row0 + grp) * APS + cc]     = pack_h2(S[nt][0], S[nt][1]);
            *(uint32_t*)&Ps[(row0 + grp + 8) * APS + cc] = pack_h2(S[nt][2], S[nt][3]);
        }
        __syncwarp();

        // ---- O += P V : ldmatrix.trans V b-frags ----
#pragma unroll
        for (int ks = 0; ks < 4; ks++) {         // k = 64 -> 4 ksteps of 16
            uint32_t a[4];
            LDMX4(a, pbase + ks * 32);
#pragma unroll
            for (int np = 0; np < 8; np++) {
                uint32_t b[4];
                LDMX4T(b, vbase[np] + ks * 16 * AKS_B);
                mma_f16(O[np*2][0], O[np*2][1], O[np*2][2], O[np*2][3],
                        a[0], a[1], a[2], a[3], b[0], b[1]);
                mma_f16(O[np*2+1][0], O[np*2+1][1], O[np*2+1][2], O[np*2+1][3],
                        a[0], a[1], a[2], a[3], b[2], b[3]);
            }
        }
    }

    // Epilogue: normalize, convert to fp16, store
    const float inv0 = 1.0f / l0;
    const float inv1 = 1.0f / l1;
    __half* dst0 = out + (size_t)(q0 + row0 + grp) * D_MODEL + hq * HD;
    __half* dst1 = out + (size_t)(q0 + row0 + grp + 8) * D_MODEL + hq * HD;
#pragma unroll
    for (int nt = 0; nt < 16; nt++) {
        const int cc = nt * 8 + 2 * qid;
        *(uint32_t*)&dst0[cc] = pack_h2(O[nt][0] * inv0, O[nt][1] * inv0);
        *(uint32_t*)&dst1[cc] = pack_h2(O[nt][2] * inv1, O[nt][3] * inv1);
    }
}

// ---------------------------------------------------------------------------
// Launch
// ---------------------------------------------------------------------------
extern "C" void kernel_launch(void* const* d_in, const int* in_sizes, int n_in,
                              void* d_out, int out_size)
{
    const float* x    = (const float*)d_in[0];  // (1, 2048, 2048)
    const float* Wqkv = (const float*)d_in[1];  // (2048, 3072)
    const float* Wo   = (const float*)d_in[2];  // (2048, 2048)
    const float* s    = (const float*)d_in[3];  // (1, 16)
    float* out = (float*)d_out;                 // (1, 2048, 2048)

    __half *xh, *wqkvth, *woth, *projh, *attnh;
    float* proj;
    cudaGetSymbolAddress((void**)&xh, g_xh);
    cudaGetSymbolAddress((void**)&wqkvth, g_wqkvth);
    cudaGetSymbolAddress((void**)&woth, g_woth);
    cudaGetSymbolAddress((void**)&proj, g_proj);
    cudaGetSymbolAddress((void**)&projh, g_projh);
    cudaGetSymbolAddress((void**)&attnh, g_attnh);

    // 0) Pre-pass: x -> fp16; weights -> transposed fp16
    {
        int n4 = L_SEQ * D_MODEL / 4;
        cvt_h_kernel<<<(n4 + 255) / 256, 256>>>(x, xh, n4);
        dim3 blk(32, 8);
        transpose_cvt_h_kernel<<<dim3(QKV_DIM / 32, D_MODEL / 32), blk>>>(Wqkv, wqkvth, D_MODEL, QKV_DIM);
        transpose_cvt_h_kernel<<<dim3(D_MODEL / 32, D_MODEL / 32), blk>>>(Wo, woth, D_MODEL, D_MODEL);
    }

    const size_t gemm_smem = 4 * HSTAGE * sizeof(__half);   // 40960 B
    cudaFuncSetAttribute(gemm_f16_kernel, cudaFuncAttributeMaxDynamicSharedMemorySize, (int)gemm_smem);

    // 1) QKV projection (fp16 GEMM)
    {
        dim3 grid(QKV_DIM / 128, L_SEQ / 128);
        gemm_f16_kernel<<<grid, 256, gemm_smem>>>(xh, wqkvth, proj, L_SEQ, QKV_DIM, D_MODEL);
    }

    // 2) RoPE + convert to fp16
    {
        dim3 grid(L_SEQ, NQH + 2 * NKVH);
        rope_cvt_h_kernel<<<grid, 64>>>(proj, projh);
    }

    // 3) Fused attention (fp16)
    {
        size_t smem = (size_t)(2 * 64 * AKS) * sizeof(__half);   // 34816 B
        cudaFuncSetAttribute(attn_f16_kernel, cudaFuncAttributeMaxDynamicSharedMemorySize, (int)smem);
        dim3 grid(L_SEQ / AT_BQ, NQH);
        attn_f16_kernel<<<grid, 128, smem>>>(projh, s, attnh);
    }

    // 4) Output projection (fp16 GEMM)
    {
        dim3 grid(D_MODEL / 128, L_SEQ / 128);
        gemm_f16_kernel<<<grid, 256, gemm_smem>>>(attnh, woth, out, L_SEQ, D_MODEL, D_MODEL);
    }
}